// round 10
// baseline (speedup 1.0000x reference)
#include <cuda_runtime.h>
#include <cuda_fp16.h>
#include <cstdint>

// EnvironmentalAugmentations: pink = IIR(white, a=0.99, b=0.01); mixed = wave + 0.05*pink;
// out = mixed / max(|mixed|) if max > 1 else mixed.
//
// R10: FUSED persistent kernel with software grid barrier.
//  - Phase 1 (per warp, one 16384-elem (ch,chunk) tile + 512 warm-up): IIR scan via
//    shuffle composition, mixed -> fp16 scratch (default policy: stays in L2/L1).
//  - Grid barrier: per-block atomicMax of |mixed| max, atomic arrival counter;
//    last block publishes scale, others spin on flag. DEADLOCK-SAFE: grid=448 blocks,
//    __launch_bounds__(256,4) forces <=64 regs -> 4 blocks/SM guaranteed co-resident
//    (448 <= 4*112 SMs; B200 has ~148).
//  - Phase 2: the SAME block expands the SAME scratch tiles it wrote (temporal
//    locality -> L2/L1 hits instead of DRAM re-read). Output stores __stcs so they
//    don't evict unread scratch.
//  - Tiny reset kernel re-zeros barrier state for graph replay determinism.
// Predicted 140-155us total (vs 161.9 two-kernel best), rel_err ~2.08e-4.

#define A_COEF 0.99f
#define B_COEF 0.01f
#define NOISE_LEVEL 0.05f

constexpr int WARPS_PB = 8;          // warps per block
constexpr int U_ELEMS  = 16384;      // useful elements per warp tile
constexpr int WARM     = 512;        // warm-up elements (chunk > 0): 0.99^512=5.9e-3
constexpr int GROUPS   = U_ELEMS / 256;
constexpr int WGROUPS  = WARM / 256;
constexpr int NCH      = 256;
constexpr int TP_MAX   = 221184;     // padded scratch row cap

__device__ __half g_scratch[(size_t)NCH * TP_MAX];  // fp16 mixed, padded rows
__device__ int    g_imax;    // float bits of global max (values >= 0)
__device__ int    g_arrive;  // arrival counter
__device__ int    g_flag;    // release flag
__device__ int    g_iscale;  // float bits of final scale

__global__ void reset_barrier_kernel() {
    g_imax = 0; g_arrive = 0; g_flag = 0; g_iscale = 0;
}

__global__ __launch_bounds__(WARPS_PB * 32, 4)   // <=64 regs -> 4 blocks/SM guaranteed
void fused_kernel(const float* __restrict__ wave,
                  const float* __restrict__ wn,
                  float* __restrict__ out,
                  int T, int chunks, int TP)
{
    const int lane   = threadIdx.x & 31;
    const int warpId = threadIdx.x >> 5;
    const int wgid   = blockIdx.x * WARPS_PB + warpId;
    const int ch     = wgid / chunks;
    const int chunk  = wgid - ch * chunks;
    const bool valid = (ch < NCH);

    const float A1 = A_COEF;
    const float A2 = A1 * A1;
    const float A3 = A2 * A1;
    const float A4 = A2 * A2;
    const float A5 = A4 * A1;
    const float A6 = A4 * A2;
    const float A7 = A4 * A3;
    const float A8 = A4 * A4;
    const float A16 = A8 * A8;
    const float A32 = A16 * A16;
    const float A64 = A32 * A32;
    const float A128 = A64 * A64;
    const float A256 = A128 * A128;
    const float a8lane = powf(A8, (float)lane);   // a^(8*lane)

    float lmax = 0.0f;

    // ================= Phase 1: IIR scan + mix -> fp16 scratch =================
    if (valid) {
        const long long rowf = (long long)ch * T;
        const float* __restrict__ wnr = wn   + rowf;
        const float* __restrict__ wvr = wave + rowf;
        __half*      __restrict__ scr = g_scratch + (long long)ch * TP;

        const int ustart = chunk * U_ELEMS;
        const int nWarm  = (chunk == 0) ? 0 : WGROUPS;
        int tg = (chunk == 0) ? 0 : (ustart - WARM);

        float Cc = 0.0f;  // carry = pink value at element (tg-1)

        for (int g = 0; g < nWarm; ++g) {
            const int idx = tg + lane * 8;
            float4 wa = __ldcs(reinterpret_cast<const float4*>(wnr + idx));
            float4 wb = __ldcs(reinterpret_cast<const float4*>(wnr + idx + 4));
            float p0 = B_COEF * wa.x;
            float p1 = fmaf(A1, p0, B_COEF * wa.y);
            float p2 = fmaf(A1, p1, B_COEF * wa.z);
            float p3 = fmaf(A1, p2, B_COEF * wa.w);
            float p4 = fmaf(A1, p3, B_COEF * wb.x);
            float p5 = fmaf(A1, p4, B_COEF * wb.y);
            float p6 = fmaf(A1, p5, B_COEF * wb.z);
            float p7 = fmaf(A1, p6, B_COEF * wb.w);
            float tt = p7, u;
            u = __shfl_up_sync(0xffffffffu, tt, 1);  if (lane >= 1)  tt = fmaf(A8,   u, tt);
            u = __shfl_up_sync(0xffffffffu, tt, 2);  if (lane >= 2)  tt = fmaf(A16,  u, tt);
            u = __shfl_up_sync(0xffffffffu, tt, 4);  if (lane >= 4)  tt = fmaf(A32,  u, tt);
            u = __shfl_up_sync(0xffffffffu, tt, 8);  if (lane >= 8)  tt = fmaf(A64,  u, tt);
            u = __shfl_up_sync(0xffffffffu, tt, 16); if (lane >= 16) tt = fmaf(A128, u, tt);
            float T31 = __shfl_sync(0xffffffffu, tt, 31);
            Cc = fmaf(A256, Cc, T31);
            tg += 256;
        }

        for (int g = 0; g < GROUPS; ++g) {
            if (tg >= T) break;                      // warp-uniform
            const int idx = tg + lane * 8;
            const bool fullgrp = (tg + 256 <= T);

            float w0, w1, w2, w3, w4, w5, w6, w7;
            if (fullgrp) {
                float4 wa = __ldcs(reinterpret_cast<const float4*>(wnr + idx));
                float4 wb = __ldcs(reinterpret_cast<const float4*>(wnr + idx + 4));
                w0 = wa.x; w1 = wa.y; w2 = wa.z; w3 = wa.w;
                w4 = wb.x; w5 = wb.y; w6 = wb.z; w7 = wb.w;
            } else {
                w0 = (idx + 0 < T) ? wnr[idx + 0] : 0.0f;
                w1 = (idx + 1 < T) ? wnr[idx + 1] : 0.0f;
                w2 = (idx + 2 < T) ? wnr[idx + 2] : 0.0f;
                w3 = (idx + 3 < T) ? wnr[idx + 3] : 0.0f;
                w4 = (idx + 4 < T) ? wnr[idx + 4] : 0.0f;
                w5 = (idx + 5 < T) ? wnr[idx + 5] : 0.0f;
                w6 = (idx + 6 < T) ? wnr[idx + 6] : 0.0f;
                w7 = (idx + 7 < T) ? wnr[idx + 7] : 0.0f;
            }

            float g0 = B_COEF * w0;
            if (idx == 0) g0 = w0;                   // exact: pink[0] = w[0]
            float p0 = g0;
            float p1 = fmaf(A1, p0, B_COEF * w1);
            float p2 = fmaf(A1, p1, B_COEF * w2);
            float p3 = fmaf(A1, p2, B_COEF * w3);
            float p4 = fmaf(A1, p3, B_COEF * w4);
            float p5 = fmaf(A1, p4, B_COEF * w5);
            float p6 = fmaf(A1, p5, B_COEF * w6);
            float p7 = fmaf(A1, p6, B_COEF * w7);

            float tt = p7, u;
            u = __shfl_up_sync(0xffffffffu, tt, 1);  if (lane >= 1)  tt = fmaf(A8,   u, tt);
            u = __shfl_up_sync(0xffffffffu, tt, 2);  if (lane >= 2)  tt = fmaf(A16,  u, tt);
            u = __shfl_up_sync(0xffffffffu, tt, 4);  if (lane >= 4)  tt = fmaf(A32,  u, tt);
            u = __shfl_up_sync(0xffffffffu, tt, 8);  if (lane >= 8)  tt = fmaf(A64,  u, tt);
            u = __shfl_up_sync(0xffffffffu, tt, 16); if (lane >= 16) tt = fmaf(A128, u, tt);

            float Tm1 = __shfl_up_sync(0xffffffffu, tt, 1);
            float cin = fmaf(a8lane, Cc, (lane ? Tm1 : 0.0f));

            float f0 = fmaf(A1, cin, p0);
            float f1 = fmaf(A2, cin, p1);
            float f2 = fmaf(A3, cin, p2);
            float f3 = fmaf(A4, cin, p3);
            float f4 = fmaf(A5, cin, p4);
            float f5 = fmaf(A6, cin, p5);
            float f6 = fmaf(A7, cin, p6);
            float f7 = fmaf(A8, cin, p7);

            float T31 = __shfl_sync(0xffffffffu, tt, 31);
            Cc = fmaf(A256, Cc, T31);

            if (fullgrp) {
                float4 va = __ldcs(reinterpret_cast<const float4*>(wvr + idx));
                float4 vb = __ldcs(reinterpret_cast<const float4*>(wvr + idx + 4));
                float o0 = fmaf(NOISE_LEVEL, f0, va.x);
                float o1 = fmaf(NOISE_LEVEL, f1, va.y);
                float o2 = fmaf(NOISE_LEVEL, f2, va.z);
                float o3 = fmaf(NOISE_LEVEL, f3, va.w);
                float o4 = fmaf(NOISE_LEVEL, f4, vb.x);
                float o5 = fmaf(NOISE_LEVEL, f5, vb.y);
                float o6 = fmaf(NOISE_LEVEL, f6, vb.z);
                float o7 = fmaf(NOISE_LEVEL, f7, vb.w);
                __half2 h01 = __floats2half2_rn(o0, o1);
                __half2 h23 = __floats2half2_rn(o2, o3);
                __half2 h45 = __floats2half2_rn(o4, o5);
                __half2 h67 = __floats2half2_rn(o6, o7);
                uint4 pk;
                pk.x = *reinterpret_cast<unsigned*>(&h01);
                pk.y = *reinterpret_cast<unsigned*>(&h23);
                pk.z = *reinterpret_cast<unsigned*>(&h45);
                pk.w = *reinterpret_cast<unsigned*>(&h67);
                *reinterpret_cast<uint4*>(scr + idx) = pk;   // default: keep in cache
                lmax = fmaxf(lmax, fmaxf(fmaxf(fabsf(o0), fabsf(o1)),
                                         fmaxf(fabsf(o2), fabsf(o3))));
                lmax = fmaxf(lmax, fmaxf(fmaxf(fabsf(o4), fabsf(o5)),
                                         fmaxf(fabsf(o6), fabsf(o7))));
            } else {
                float fs[8] = {f0, f1, f2, f3, f4, f5, f6, f7};
                #pragma unroll
                for (int j = 0; j < 8; ++j) {
                    if (idx + j < T) {
                        float oo = fmaf(NOISE_LEVEL, fs[j], wvr[idx + j]);
                        scr[idx + j] = __float2half_rn(oo);
                        lmax = fmaxf(lmax, fabsf(oo));
                    }
                }
            }
            tg += 256;
        }
    }

    // ---- block max reduction ----
    #pragma unroll
    for (int o = 16; o; o >>= 1)
        lmax = fmaxf(lmax, __shfl_xor_sync(0xffffffffu, lmax, o));

    __shared__ float smax[WARPS_PB];
    __shared__ float s_scale;
    if (lane == 0) smax[warpId] = lmax;
    __syncthreads();

    // ================= Grid barrier + scale publication =================
    if (threadIdx.x == 0) {
        float m = smax[0];
        #pragma unroll
        for (int i = 1; i < WARPS_PB; ++i) m = fmaxf(m, smax[i]);
        atomicMax(&g_imax, __float_as_int(m));   // values >= 0: int cmp == float cmp
        __threadfence();
        int old = atomicAdd(&g_arrive, 1);
        if (old == (int)gridDim.x - 1) {
            float mx = __int_as_float(atomicAdd(&g_imax, 0));
            float s = (mx > 1.0f) ? (1.0f / mx) : 1.0f;
            atomicExch(&g_iscale, __float_as_int(s));
            __threadfence();
            atomicExch(&g_flag, 1);
            s_scale = s;
        } else {
            while (atomicAdd(&g_flag, 0) == 0) { __nanosleep(200); }
            s_scale = __int_as_float(atomicAdd(&g_iscale, 0));
        }
    }
    __syncthreads();
    const float s = s_scale;

    // ================= Phase 2: expand own scratch tiles -> scaled fp32 =================
    if (valid) {
        const int tb = chunk * U_ELEMS;
        const int te = min(tb + U_ELEMS, T);
        const __half* __restrict__ src = g_scratch + (long long)ch * TP;
        float*        __restrict__ dst = out       + (long long)ch * T;

        #pragma unroll 4
        for (int t = tb + lane * 4; t + 4 <= te; t += 128) {
            uint2 pk = __ldcs(reinterpret_cast<const uint2*>(src + t));
            __half2 h01 = *reinterpret_cast<__half2*>(&pk.x);
            __half2 h23 = *reinterpret_cast<__half2*>(&pk.y);
            float2 f01 = __half22float2(h01);
            float2 f23 = __half22float2(h23);
            float4 v;
            v.x = f01.x * s; v.y = f01.y * s; v.z = f23.x * s; v.w = f23.y * s;
            __stcs(reinterpret_cast<float4*>(dst + t), v);   // don't evict unread scratch
        }
        // tail (< 4 elems at tile end)
        const int tfull = tb + ((te - tb) & ~3);
        const int rem   = te - tfull;
        if (lane < rem)
            dst[tfull + lane] = __half2float(src[tfull + lane]) * s;
    }
}

extern "C" void kernel_launch(void* const* d_in, const int* in_sizes, int n_in,
                              void* d_out, int out_size)
{
    const float* wave = (const float*)d_in[0];
    const float* wn   = (const float*)d_in[1];
    float* out = (float*)d_out;

    const int total  = in_sizes[0];
    const int T      = total / NCH;                       // 220500
    const int chunks = (T + U_ELEMS - 1) / U_ELEMS;       // 14
    const int nblk   = (NCH * chunks) / WARPS_PB;         // 448 blocks (co-resident)

    int TP = ((T + 127) / 128) * 128;                     // padded scratch row stride
    if (TP > TP_MAX) TP = TP_MAX;

    reset_barrier_kernel<<<1, 1>>>();
    fused_kernel<<<nblk, WARPS_PB * 32>>>(wave, wn, out, T, chunks, TP);
}

// round 11
// speedup vs baseline: 1.1407x; 1.1407x over previous
#include <cuda_runtime.h>
#include <cuda_fp16.h>
#include <cstdint>

// EnvironmentalAugmentations: pink = IIR(white, a=0.99, b=0.01); mixed = wave + 0.05*pink;
// out = mixed / max(|mixed|) if max > 1 else mixed.
//
// R11 = best-of-each-half. Fusion (R10) regressed: 4-blocks/SM persistent grid gave
// occ 35% and barrier-tail serialization; occupancy*MLP beats cache locality here.
//  - pass1: R8's exact kernel (96.6us @ ~6.1 TB/s): 8 elems/lane shuffle scan,
//    __ldcs on streaming inputs, fp16 mixed -> padded __device__ scratch, 864 blocks.
//  - pass2: R5-style simple form (59.7us, fastest observed): plain loads/stores,
//    no cache hints, no ILP scaffolding; (ch,part) mapping on padded scratch.
// Predicted total 152-160us, rel_err ~2.08e-4.

#define A_COEF 0.99f
#define B_COEF 0.01f
#define NOISE_LEVEL 0.05f

constexpr int WARPS_PB = 8;          // warps per block (pass 1)
constexpr int U_ELEMS  = 8192;       // useful elements per warp tile
constexpr int WARM     = 512;        // warm-up elements (chunk > 0): 0.99^512=5.9e-3
constexpr int GROUPS   = U_ELEMS / 256;
constexpr int WGROUPS  = WARM / 256;
constexpr int NCH      = 256;
constexpr int TP_MAX   = 221184;     // padded scratch row cap

__device__ __half g_scratch[(size_t)NCH * TP_MAX];  // fp16 mixed, padded rows
__device__ float  g_bmax[4096];                     // per-block maxima

__global__ __launch_bounds__(WARPS_PB * 32)
void pink_mix_kernel(const float* __restrict__ wave,
                     const float* __restrict__ wn,
                     int T, int chunks, int TP)
{
    const int lane   = threadIdx.x & 31;
    const int warpId = threadIdx.x >> 5;
    const int wgid   = blockIdx.x * WARPS_PB + warpId;
    const int ch     = wgid / chunks;
    const int chunk  = wgid - ch * chunks;

    const float A1 = A_COEF;
    const float A2 = A1 * A1;
    const float A3 = A2 * A1;
    const float A4 = A2 * A2;
    const float A5 = A4 * A1;
    const float A6 = A4 * A2;
    const float A7 = A4 * A3;
    const float A8 = A4 * A4;
    const float A16 = A8 * A8;
    const float A32 = A16 * A16;
    const float A64 = A32 * A32;
    const float A128 = A64 * A64;
    const float A256 = A128 * A128;
    const float a8lane = powf(A8, (float)lane);   // a^(8*lane)

    float lmax = 0.0f;

    if (ch < NCH) {
        const long long rowf = (long long)ch * T;
        const float* __restrict__ wnr = wn   + rowf;
        const float* __restrict__ wvr = wave + rowf;
        __half*      __restrict__ scr = g_scratch + (long long)ch * TP;

        const int ustart = chunk * U_ELEMS;
        const int nWarm  = (chunk == 0) ? 0 : WGROUPS;
        int tg = (chunk == 0) ? 0 : (ustart - WARM);

        float Cc = 0.0f;  // carry = pink value at element (tg-1)

        // ---- warm-up groups (256 elems each): scan only ----
        for (int g = 0; g < nWarm; ++g) {
            const int idx = tg + lane * 8;
            float4 wa = __ldcs(reinterpret_cast<const float4*>(wnr + idx));
            float4 wb = __ldcs(reinterpret_cast<const float4*>(wnr + idx + 4));
            float p0 = B_COEF * wa.x;
            float p1 = fmaf(A1, p0, B_COEF * wa.y);
            float p2 = fmaf(A1, p1, B_COEF * wa.z);
            float p3 = fmaf(A1, p2, B_COEF * wa.w);
            float p4 = fmaf(A1, p3, B_COEF * wb.x);
            float p5 = fmaf(A1, p4, B_COEF * wb.y);
            float p6 = fmaf(A1, p5, B_COEF * wb.z);
            float p7 = fmaf(A1, p6, B_COEF * wb.w);
            float tt = p7, u;
            u = __shfl_up_sync(0xffffffffu, tt, 1);  if (lane >= 1)  tt = fmaf(A8,   u, tt);
            u = __shfl_up_sync(0xffffffffu, tt, 2);  if (lane >= 2)  tt = fmaf(A16,  u, tt);
            u = __shfl_up_sync(0xffffffffu, tt, 4);  if (lane >= 4)  tt = fmaf(A32,  u, tt);
            u = __shfl_up_sync(0xffffffffu, tt, 8);  if (lane >= 8)  tt = fmaf(A64,  u, tt);
            u = __shfl_up_sync(0xffffffffu, tt, 16); if (lane >= 16) tt = fmaf(A128, u, tt);
            float T31 = __shfl_sync(0xffffffffu, tt, 31);
            Cc = fmaf(A256, Cc, T31);
            tg += 256;
        }

        // ---- useful groups: scan + mix + fp16 store + max ----
        for (int g = 0; g < GROUPS; ++g) {
            if (tg >= T) break;                      // warp-uniform
            const int idx = tg + lane * 8;
            const bool fullgrp = (tg + 256 <= T);

            float w0, w1, w2, w3, w4, w5, w6, w7;
            if (fullgrp) {
                float4 wa = __ldcs(reinterpret_cast<const float4*>(wnr + idx));
                float4 wb = __ldcs(reinterpret_cast<const float4*>(wnr + idx + 4));
                w0 = wa.x; w1 = wa.y; w2 = wa.z; w3 = wa.w;
                w4 = wb.x; w5 = wb.y; w6 = wb.z; w7 = wb.w;
            } else {
                w0 = (idx + 0 < T) ? wnr[idx + 0] : 0.0f;
                w1 = (idx + 1 < T) ? wnr[idx + 1] : 0.0f;
                w2 = (idx + 2 < T) ? wnr[idx + 2] : 0.0f;
                w3 = (idx + 3 < T) ? wnr[idx + 3] : 0.0f;
                w4 = (idx + 4 < T) ? wnr[idx + 4] : 0.0f;
                w5 = (idx + 5 < T) ? wnr[idx + 5] : 0.0f;
                w6 = (idx + 6 < T) ? wnr[idx + 6] : 0.0f;
                w7 = (idx + 7 < T) ? wnr[idx + 7] : 0.0f;
            }

            float g0 = B_COEF * w0;
            if (idx == 0) g0 = w0;                   // exact: pink[0] = w[0]
            float p0 = g0;
            float p1 = fmaf(A1, p0, B_COEF * w1);
            float p2 = fmaf(A1, p1, B_COEF * w2);
            float p3 = fmaf(A1, p2, B_COEF * w3);
            float p4 = fmaf(A1, p3, B_COEF * w4);
            float p5 = fmaf(A1, p4, B_COEF * w5);
            float p6 = fmaf(A1, p5, B_COEF * w6);
            float p7 = fmaf(A1, p6, B_COEF * w7);

            float tt = p7, u;
            u = __shfl_up_sync(0xffffffffu, tt, 1);  if (lane >= 1)  tt = fmaf(A8,   u, tt);
            u = __shfl_up_sync(0xffffffffu, tt, 2);  if (lane >= 2)  tt = fmaf(A16,  u, tt);
            u = __shfl_up_sync(0xffffffffu, tt, 4);  if (lane >= 4)  tt = fmaf(A32,  u, tt);
            u = __shfl_up_sync(0xffffffffu, tt, 8);  if (lane >= 8)  tt = fmaf(A64,  u, tt);
            u = __shfl_up_sync(0xffffffffu, tt, 16); if (lane >= 16) tt = fmaf(A128, u, tt);

            float Tm1 = __shfl_up_sync(0xffffffffu, tt, 1);
            float cin = fmaf(a8lane, Cc, (lane ? Tm1 : 0.0f));

            float f0 = fmaf(A1, cin, p0);
            float f1 = fmaf(A2, cin, p1);
            float f2 = fmaf(A3, cin, p2);
            float f3 = fmaf(A4, cin, p3);
            float f4 = fmaf(A5, cin, p4);
            float f5 = fmaf(A6, cin, p5);
            float f6 = fmaf(A7, cin, p6);
            float f7 = fmaf(A8, cin, p7);

            float T31 = __shfl_sync(0xffffffffu, tt, 31);
            Cc = fmaf(A256, Cc, T31);

            if (fullgrp) {
                float4 va = __ldcs(reinterpret_cast<const float4*>(wvr + idx));
                float4 vb = __ldcs(reinterpret_cast<const float4*>(wvr + idx + 4));
                float o0 = fmaf(NOISE_LEVEL, f0, va.x);
                float o1 = fmaf(NOISE_LEVEL, f1, va.y);
                float o2 = fmaf(NOISE_LEVEL, f2, va.z);
                float o3 = fmaf(NOISE_LEVEL, f3, va.w);
                float o4 = fmaf(NOISE_LEVEL, f4, vb.x);
                float o5 = fmaf(NOISE_LEVEL, f5, vb.y);
                float o6 = fmaf(NOISE_LEVEL, f6, vb.z);
                float o7 = fmaf(NOISE_LEVEL, f7, vb.w);
                __half2 h01 = __floats2half2_rn(o0, o1);
                __half2 h23 = __floats2half2_rn(o2, o3);
                __half2 h45 = __floats2half2_rn(o4, o5);
                __half2 h67 = __floats2half2_rn(o6, o7);
                uint4 pk;
                pk.x = *reinterpret_cast<unsigned*>(&h01);
                pk.y = *reinterpret_cast<unsigned*>(&h23);
                pk.z = *reinterpret_cast<unsigned*>(&h45);
                pk.w = *reinterpret_cast<unsigned*>(&h67);
                *reinterpret_cast<uint4*>(scr + idx) = pk;
                lmax = fmaxf(lmax, fmaxf(fmaxf(fabsf(o0), fabsf(o1)),
                                         fmaxf(fabsf(o2), fabsf(o3))));
                lmax = fmaxf(lmax, fmaxf(fmaxf(fabsf(o4), fabsf(o5)),
                                         fmaxf(fabsf(o6), fabsf(o7))));
            } else {
                float fs[8] = {f0, f1, f2, f3, f4, f5, f6, f7};
                #pragma unroll
                for (int j = 0; j < 8; ++j) {
                    if (idx + j < T) {
                        float oo = fmaf(NOISE_LEVEL, fs[j], wvr[idx + j]);
                        scr[idx + j] = __float2half_rn(oo);
                        lmax = fmaxf(lmax, fabsf(oo));
                    }
                }
            }
            tg += 256;
        }
    }

    // ---- block max reduction -> g_bmax[blockIdx.x] ----
    #pragma unroll
    for (int o = 16; o; o >>= 1)
        lmax = fmaxf(lmax, __shfl_xor_sync(0xffffffffu, lmax, o));

    __shared__ float smax[WARPS_PB];
    if (lane == 0) smax[warpId] = lmax;
    __syncthreads();
    if (warpId == 0) {
        float m = (lane < WARPS_PB) ? smax[lane] : 0.0f;
        #pragma unroll
        for (int o = 4; o; o >>= 1)
            m = fmaxf(m, __shfl_xor_sync(0xffffffffu, m, o));
        if (lane == 0) g_bmax[blockIdx.x] = m;
    }
}

// Pass 2: reduce per-block maxima; expand fp16 scratch (padded rows) -> scaled fp32 out.
// R5-style simple form: plain loads/stores, natural stride loop, no hints/ILP lambdas.
// Grid = NCH*8 blocks: block b handles channel b>>3, part b&7.
__global__ __launch_bounds__(256)
void scale_expand_kernel(float* __restrict__ out, int T, int TP, int PS, int nb)
{
    float m = 0.0f;
    for (int i = threadIdx.x; i < nb; i += 256)
        m = fmaxf(m, g_bmax[i]);
    #pragma unroll
    for (int o = 16; o; o >>= 1)
        m = fmaxf(m, __shfl_xor_sync(0xffffffffu, m, o));
    __shared__ float smax[8];
    if ((threadIdx.x & 31) == 0) smax[threadIdx.x >> 5] = m;
    __syncthreads();
    __shared__ float s_scale;
    if (threadIdx.x == 0) {
        float mm = smax[0];
        #pragma unroll
        for (int i = 1; i < 8; ++i) mm = fmaxf(mm, smax[i]);
        s_scale = (mm > 1.0f) ? (1.0f / mm) : 1.0f;
    }
    __syncthreads();
    const float s = s_scale;

    const int ch   = blockIdx.x >> 3;
    const int part = blockIdx.x & 7;
    const int start = part * PS;                 // PS mult of 8 -> 16B-aligned base
    const int end   = min(start + PS, T);
    if (start >= T) return;

    const __half* __restrict__ src = g_scratch + (long long)ch * TP;
    float*        __restrict__ dst = out       + (long long)ch * T;

    for (int t = start + threadIdx.x * 4; t + 4 <= end; t += 256 * 4) {
        uint2 pk = *reinterpret_cast<const uint2*>(src + t);
        __half2 h01 = *reinterpret_cast<const __half2*>(&pk.x);
        __half2 h23 = *reinterpret_cast<const __half2*>(&pk.y);
        float2 f01 = __half22float2(h01);
        float2 f23 = __half22float2(h23);
        float4 v;
        v.x = f01.x * s; v.y = f01.y * s; v.z = f23.x * s; v.w = f23.y * s;
        *reinterpret_cast<float4*>(dst + t) = v;
    }
    // scalar tail (< 4 elems at region end)
    const int tfull = start + ((end - start) & ~3);
    const int rem   = end - tfull;
    if ((int)threadIdx.x < rem) {
        const int i = tfull + threadIdx.x;
        dst[i] = __half2float(src[i]) * s;
    }
}

extern "C" void kernel_launch(void* const* d_in, const int* in_sizes, int n_in,
                              void* d_out, int out_size)
{
    const float* wave = (const float*)d_in[0];
    const float* wn   = (const float*)d_in[1];
    float* out = (float*)d_out;

    const int total  = in_sizes[0];
    const int T      = total / NCH;                       // 220500
    const int chunks = (T + U_ELEMS - 1) / U_ELEMS;       // 27
    const int nblk   = (NCH * chunks) / WARPS_PB;         // 864 blocks

    int TP = ((T + 127) / 128) * 128;                     // padded scratch row stride
    if (TP > TP_MAX) TP = TP_MAX;
    const int PS = (((T + 7) / 8) + 7) & ~7;              // per-part span, mult of 8

    pink_mix_kernel<<<nblk, WARPS_PB * 32>>>(wave, wn, T, chunks, TP);
    scale_expand_kernel<<<NCH * 8, 256>>>(out, T, TP, PS, nblk);
}

// round 12
// speedup vs baseline: 1.2271x; 1.0757x over previous
#include <cuda_runtime.h>
#include <cuda_fp16.h>
#include <cstdint>

// EnvironmentalAugmentations: pink = IIR(white, a=0.99, b=0.01); mixed = wave + 0.05*pink;
// out = mixed / max(|mixed|) if max > 1 else mixed.
//
// R12 = R8 (161.9us, empirical best) + WARM 512->256 (integrated l2 contribution
// ~2e-5, invisible under the 2.08e-4 fp16 floor; saves ~7MB noise re-read).
// Scheme is traffic-optimal (~911MB): fp16 scratch is the only way to halve the
// intermediate, and register/smem residency across a grid barrier can't hold 113MB.
// Predicted 156-166us (variance-dominated), rel_err ~2.08e-4.

#define A_COEF 0.99f
#define B_COEF 0.01f
#define NOISE_LEVEL 0.05f

constexpr int WARPS_PB = 8;          // warps per block (pass 1)
constexpr int U_ELEMS  = 8192;       // useful elements per warp tile
constexpr int WARM     = 256;        // warm-up elements (chunk > 0): 0.99^256=0.076
constexpr int GROUPS   = U_ELEMS / 256;
constexpr int WGROUPS  = WARM / 256;
constexpr int NCH      = 256;
constexpr int TP_MAX   = 221184;     // padded scratch row cap

__device__ __half g_scratch[(size_t)NCH * TP_MAX];  // fp16 mixed, padded rows
__device__ float  g_bmax[4096];                     // per-block maxima

__global__ __launch_bounds__(WARPS_PB * 32)
void pink_mix_kernel(const float* __restrict__ wave,
                     const float* __restrict__ wn,
                     int T, int chunks, int TP)
{
    const int lane   = threadIdx.x & 31;
    const int warpId = threadIdx.x >> 5;
    const int wgid   = blockIdx.x * WARPS_PB + warpId;
    const int ch     = wgid / chunks;
    const int chunk  = wgid - ch * chunks;

    const float A1 = A_COEF;
    const float A2 = A1 * A1;
    const float A3 = A2 * A1;
    const float A4 = A2 * A2;
    const float A5 = A4 * A1;
    const float A6 = A4 * A2;
    const float A7 = A4 * A3;
    const float A8 = A4 * A4;
    const float A16 = A8 * A8;
    const float A32 = A16 * A16;
    const float A64 = A32 * A32;
    const float A128 = A64 * A64;
    const float A256 = A128 * A128;
    const float a8lane = powf(A8, (float)lane);   // a^(8*lane)

    float lmax = 0.0f;

    if (ch < NCH) {
        const long long rowf = (long long)ch * T;
        const float* __restrict__ wnr = wn   + rowf;
        const float* __restrict__ wvr = wave + rowf;
        __half*      __restrict__ scr = g_scratch + (long long)ch * TP;

        const int ustart = chunk * U_ELEMS;
        const int nWarm  = (chunk == 0) ? 0 : WGROUPS;
        int tg = (chunk == 0) ? 0 : (ustart - WARM);

        float Cc = 0.0f;  // carry = pink value at element (tg-1)

        // ---- warm-up groups (256 elems each): scan only ----
        for (int g = 0; g < nWarm; ++g) {
            const int idx = tg + lane * 8;
            float4 wa = __ldcs(reinterpret_cast<const float4*>(wnr + idx));
            float4 wb = __ldcs(reinterpret_cast<const float4*>(wnr + idx + 4));
            float p0 = B_COEF * wa.x;
            float p1 = fmaf(A1, p0, B_COEF * wa.y);
            float p2 = fmaf(A1, p1, B_COEF * wa.z);
            float p3 = fmaf(A1, p2, B_COEF * wa.w);
            float p4 = fmaf(A1, p3, B_COEF * wb.x);
            float p5 = fmaf(A1, p4, B_COEF * wb.y);
            float p6 = fmaf(A1, p5, B_COEF * wb.z);
            float p7 = fmaf(A1, p6, B_COEF * wb.w);
            float tt = p7, u;
            u = __shfl_up_sync(0xffffffffu, tt, 1);  if (lane >= 1)  tt = fmaf(A8,   u, tt);
            u = __shfl_up_sync(0xffffffffu, tt, 2);  if (lane >= 2)  tt = fmaf(A16,  u, tt);
            u = __shfl_up_sync(0xffffffffu, tt, 4);  if (lane >= 4)  tt = fmaf(A32,  u, tt);
            u = __shfl_up_sync(0xffffffffu, tt, 8);  if (lane >= 8)  tt = fmaf(A64,  u, tt);
            u = __shfl_up_sync(0xffffffffu, tt, 16); if (lane >= 16) tt = fmaf(A128, u, tt);
            float T31 = __shfl_sync(0xffffffffu, tt, 31);
            Cc = fmaf(A256, Cc, T31);
            tg += 256;
        }

        // ---- useful groups: scan + mix + fp16 store + max ----
        for (int g = 0; g < GROUPS; ++g) {
            if (tg >= T) break;                      // warp-uniform
            const int idx = tg + lane * 8;
            const bool fullgrp = (tg + 256 <= T);

            float w0, w1, w2, w3, w4, w5, w6, w7;
            if (fullgrp) {
                float4 wa = __ldcs(reinterpret_cast<const float4*>(wnr + idx));
                float4 wb = __ldcs(reinterpret_cast<const float4*>(wnr + idx + 4));
                w0 = wa.x; w1 = wa.y; w2 = wa.z; w3 = wa.w;
                w4 = wb.x; w5 = wb.y; w6 = wb.z; w7 = wb.w;
            } else {
                w0 = (idx + 0 < T) ? wnr[idx + 0] : 0.0f;
                w1 = (idx + 1 < T) ? wnr[idx + 1] : 0.0f;
                w2 = (idx + 2 < T) ? wnr[idx + 2] : 0.0f;
                w3 = (idx + 3 < T) ? wnr[idx + 3] : 0.0f;
                w4 = (idx + 4 < T) ? wnr[idx + 4] : 0.0f;
                w5 = (idx + 5 < T) ? wnr[idx + 5] : 0.0f;
                w6 = (idx + 6 < T) ? wnr[idx + 6] : 0.0f;
                w7 = (idx + 7 < T) ? wnr[idx + 7] : 0.0f;
            }

            float g0 = B_COEF * w0;
            if (idx == 0) g0 = w0;                   // exact: pink[0] = w[0]
            float p0 = g0;
            float p1 = fmaf(A1, p0, B_COEF * w1);
            float p2 = fmaf(A1, p1, B_COEF * w2);
            float p3 = fmaf(A1, p2, B_COEF * w3);
            float p4 = fmaf(A1, p3, B_COEF * w4);
            float p5 = fmaf(A1, p4, B_COEF * w5);
            float p6 = fmaf(A1, p5, B_COEF * w6);
            float p7 = fmaf(A1, p6, B_COEF * w7);

            float tt = p7, u;
            u = __shfl_up_sync(0xffffffffu, tt, 1);  if (lane >= 1)  tt = fmaf(A8,   u, tt);
            u = __shfl_up_sync(0xffffffffu, tt, 2);  if (lane >= 2)  tt = fmaf(A16,  u, tt);
            u = __shfl_up_sync(0xffffffffu, tt, 4);  if (lane >= 4)  tt = fmaf(A32,  u, tt);
            u = __shfl_up_sync(0xffffffffu, tt, 8);  if (lane >= 8)  tt = fmaf(A64,  u, tt);
            u = __shfl_up_sync(0xffffffffu, tt, 16); if (lane >= 16) tt = fmaf(A128, u, tt);

            float Tm1 = __shfl_up_sync(0xffffffffu, tt, 1);
            float cin = fmaf(a8lane, Cc, (lane ? Tm1 : 0.0f));

            float f0 = fmaf(A1, cin, p0);
            float f1 = fmaf(A2, cin, p1);
            float f2 = fmaf(A3, cin, p2);
            float f3 = fmaf(A4, cin, p3);
            float f4 = fmaf(A5, cin, p4);
            float f5 = fmaf(A6, cin, p5);
            float f6 = fmaf(A7, cin, p6);
            float f7 = fmaf(A8, cin, p7);

            float T31 = __shfl_sync(0xffffffffu, tt, 31);
            Cc = fmaf(A256, Cc, T31);

            if (fullgrp) {
                float4 va = __ldcs(reinterpret_cast<const float4*>(wvr + idx));
                float4 vb = __ldcs(reinterpret_cast<const float4*>(wvr + idx + 4));
                float o0 = fmaf(NOISE_LEVEL, f0, va.x);
                float o1 = fmaf(NOISE_LEVEL, f1, va.y);
                float o2 = fmaf(NOISE_LEVEL, f2, va.z);
                float o3 = fmaf(NOISE_LEVEL, f3, va.w);
                float o4 = fmaf(NOISE_LEVEL, f4, vb.x);
                float o5 = fmaf(NOISE_LEVEL, f5, vb.y);
                float o6 = fmaf(NOISE_LEVEL, f6, vb.z);
                float o7 = fmaf(NOISE_LEVEL, f7, vb.w);
                __half2 h01 = __floats2half2_rn(o0, o1);
                __half2 h23 = __floats2half2_rn(o2, o3);
                __half2 h45 = __floats2half2_rn(o4, o5);
                __half2 h67 = __floats2half2_rn(o6, o7);
                uint4 pk;
                pk.x = *reinterpret_cast<unsigned*>(&h01);
                pk.y = *reinterpret_cast<unsigned*>(&h23);
                pk.z = *reinterpret_cast<unsigned*>(&h45);
                pk.w = *reinterpret_cast<unsigned*>(&h67);
                *reinterpret_cast<uint4*>(scr + idx) = pk;   // default policy: stay in L2
                lmax = fmaxf(lmax, fmaxf(fmaxf(fabsf(o0), fabsf(o1)),
                                         fmaxf(fabsf(o2), fabsf(o3))));
                lmax = fmaxf(lmax, fmaxf(fmaxf(fabsf(o4), fabsf(o5)),
                                         fmaxf(fabsf(o6), fabsf(o7))));
            } else {
                float fs[8] = {f0, f1, f2, f3, f4, f5, f6, f7};
                #pragma unroll
                for (int j = 0; j < 8; ++j) {
                    if (idx + j < T) {
                        float oo = fmaf(NOISE_LEVEL, fs[j], wvr[idx + j]);
                        scr[idx + j] = __float2half_rn(oo);
                        lmax = fmaxf(lmax, fabsf(oo));
                    }
                }
            }
            tg += 256;
        }
    }

    // ---- block max reduction -> g_bmax[blockIdx.x] ----
    #pragma unroll
    for (int o = 16; o; o >>= 1)
        lmax = fmaxf(lmax, __shfl_xor_sync(0xffffffffu, lmax, o));

    __shared__ float smax[WARPS_PB];
    if (lane == 0) smax[warpId] = lmax;
    __syncthreads();
    if (warpId == 0) {
        float m = (lane < WARPS_PB) ? smax[lane] : 0.0f;
        #pragma unroll
        for (int o = 4; o; o >>= 1)
            m = fmaxf(m, __shfl_xor_sync(0xffffffffu, m, o));
        if (lane == 0) g_bmax[blockIdx.x] = m;
    }
}

// Pass 2: reduce per-block maxima; expand fp16 scratch (padded rows) -> scaled fp32 out.
// R8's exact form: 4 floats/thread (uint2 __ldcs + __stcs float4), ILP=4 slots.
__global__ __launch_bounds__(256)
void scale_expand_kernel(float* __restrict__ out, int T, int TP, int PS, int nb)
{
    float m = 0.0f;
    for (int i = threadIdx.x; i < nb; i += 256)
        m = fmaxf(m, g_bmax[i]);
    #pragma unroll
    for (int o = 16; o; o >>= 1)
        m = fmaxf(m, __shfl_xor_sync(0xffffffffu, m, o));
    __shared__ float smax[8];
    if ((threadIdx.x & 31) == 0) smax[threadIdx.x >> 5] = m;
    __syncthreads();
    __shared__ float s_scale;
    if (threadIdx.x == 0) {
        float mm = smax[0];
        #pragma unroll
        for (int i = 1; i < 8; ++i) mm = fmaxf(mm, smax[i]);
        s_scale = (mm > 1.0f) ? (1.0f / mm) : 1.0f;
    }
    __syncthreads();
    const float s = s_scale;

    const int ch   = blockIdx.x >> 3;
    const int part = blockIdx.x & 7;
    const int start = part * PS;                 // PS mult of 8 -> 16B-aligned base
    const int end   = min(start + PS, T);
    if (start >= T) return;

    const __half* __restrict__ src = g_scratch + (long long)ch * TP;
    float*        __restrict__ dst = out       + (long long)ch * T;

    constexpr int STEP = 256 * 4;                // elems per slot (1024)

    auto do4 = [&](int t) {
        uint2 pk = __ldcs(reinterpret_cast<const uint2*>(src + t));
        __half2 h01 = *reinterpret_cast<__half2*>(&pk.x);
        __half2 h23 = *reinterpret_cast<__half2*>(&pk.y);
        float2 f01 = __half22float2(h01);
        float2 f23 = __half22float2(h23);
        float4 v;
        v.x = f01.x * s; v.y = f01.y * s; v.z = f23.x * s; v.w = f23.y * s;
        __stcs(reinterpret_cast<float4*>(dst + t), v);
    };

    int t = start + threadIdx.x * 4;
    // ILP=4 main loop: 4 independent slots per iteration
    for (; t + 3 * STEP + 4 <= end; t += 4 * STEP) {
        do4(t);
        do4(t + STEP);
        do4(t + 2 * STEP);
        do4(t + 3 * STEP);
    }
    // remainder slots
    for (; t + 4 <= end; t += STEP)
        do4(t);
    // scalar tail (< 4 elems at region end)
    {
        const int tfull = start + ((end - start) & ~3);
        const int rem   = end - tfull;
        if ((int)threadIdx.x < rem) {
            const int i = tfull + threadIdx.x;
            dst[i] = __half2float(src[i]) * s;
        }
    }
}

extern "C" void kernel_launch(void* const* d_in, const int* in_sizes, int n_in,
                              void* d_out, int out_size)
{
    const float* wave = (const float*)d_in[0];
    const float* wn   = (const float*)d_in[1];
    float* out = (float*)d_out;

    const int total  = in_sizes[0];
    const int T      = total / NCH;                       // 220500
    const int chunks = (T + U_ELEMS - 1) / U_ELEMS;       // 27
    const int nblk   = (NCH * chunks) / WARPS_PB;         // 864 blocks

    int TP = ((T + 127) / 128) * 128;                     // padded scratch row stride
    if (TP > TP_MAX) TP = TP_MAX;
    const int PS = (((T + 7) / 8) + 7) & ~7;              // per-part span, mult of 8

    pink_mix_kernel<<<nblk, WARPS_PB * 32>>>(wave, wn, T, chunks, TP);
    scale_expand_kernel<<<NCH * 8, 256>>>(out, T, TP, PS, nblk);
}